// round 11
// baseline (speedup 1.0000x reference)
#include <cuda_runtime.h>
#include <cuda_bf16.h>
#include <math.h>
#include <stdint.h>

#define NN 50000
#define EE 800000
#define ETOT (EE + NN)

// ---------------- device scratch ----------------
__device__ __align__(16) float g_h[NN * 64];     // GEMM output (fp32 gather source)
__device__ __align__(16) float g_as[NN * 4];
__device__ __align__(16) float g_ad[NN * 4];
__device__ __align__(16) __nv_bfloat16 g_a3[(size_t)NN * 768];  // X bf16 triple [xh,xl,xh]
__device__ __align__(16) __nv_bfloat16 g_f3[(size_t)NN * 192];  // feat bf16 triple
__device__ __align__(16) __nv_bfloat16 g_b31[64 * 768];         // W1 triple [wh,wh,wl], [n][k]
__device__ __align__(16) __nv_bfloat16 g_b32[64 * 192];
__device__ __align__(16) __nv_bfloat16 g_b33[40 * 192];
__device__ int g_deg[NN];
__device__ int g_rowptr[NN + 1];
__device__ int g_cursor[NN];
__device__ int g_csr[ETOT];

// ---------------- fp32 -> bf16 split ----------------
__device__ __forceinline__ void split3(float x, unsigned short& h, unsigned short& l) {
    __nv_bfloat16 hb = __float2bfloat16(x);
    float lo = x - __bfloat162float(hb);
    __nv_bfloat16 lb = __float2bfloat16(lo);
    h = *(unsigned short*)&hb;
    l = *(unsigned short*)&lb;
}

// X [NN,256] fp32 -> g_a3 [NN,768] triple
__global__ void x3_kernel(const float* __restrict__ X) {
    int idx = blockIdx.x * blockDim.x + threadIdx.x;
    if (idx >= NN * 32) return;
    int n = idx >> 5, g = idx & 31;
    const float* xp = X + (size_t)n * 256 + g * 8;
    union { unsigned short s[24]; uint4 q[3]; } u;
#pragma unroll
    for (int j = 0; j < 8; j++) {
        unsigned short h, l;
        split3(xp[j], h, l);
        u.s[3 * j] = h; u.s[3 * j + 1] = l; u.s[3 * j + 2] = h;
    }
    uint4* out = (uint4*)((char*)g_a3 + (size_t)n * 1536 + g * 48);
    out[0] = u.q[0]; out[1] = u.q[1]; out[2] = u.q[2];
}

// W [FIN,FOUT] fp32 -> B3 [FOUT][3*FIN] triple (K-major rows)
template <int FIN, int FOUT>
__global__ void w3_kernel(const float* __restrict__ W, __nv_bfloat16* __restrict__ B3) {
    int idx = blockIdx.x * blockDim.x + threadIdx.x;
    if (idx >= FIN * FOUT) return;
    int k = idx / FOUT, f = idx % FOUT;
    unsigned short h, l;
    split3(W[idx], h, l);
    unsigned short* bp = (unsigned short*)(B3 + (size_t)f * (3 * FIN) + 3 * k);
    bp[0] = h; bp[1] = h; bp[2] = l;
}

// ---------------- mma.sync bf16 m16n8k16 ----------------
__device__ __forceinline__ void mma16816(float* c, const uint32_t* a, const uint32_t* b) {
    asm volatile(
        "mma.sync.aligned.m16n8k16.row.col.f32.bf16.bf16.f32 "
        "{%0,%1,%2,%3}, {%4,%5,%6,%7}, {%8,%9}, {%0,%1,%2,%3};"
        : "+f"(c[0]), "+f"(c[1]), "+f"(c[2]), "+f"(c[3])
        : "r"(a[0]), "r"(a[1]), "r"(a[2]), "r"(a[3]), "r"(b[0]), "r"(b[1]));
}

// ---------------- GEMM: C[128-tile, FOUT] = A3[NN,K3] * B3[FOUT,K3]^T ----------------
// 256 threads = 8 warps. Warp (wid&3): rows wm=32*(wid&3); (wid>>2): cols wn=32*(wid>>2).
template <int K3, int FOUT, bool ALPHA>
__global__ void __launch_bounds__(256) mma_gemm(
    const __nv_bfloat16* __restrict__ A3, const __nv_bfloat16* __restrict__ B3,
    float* __restrict__ C, const float* __restrict__ asrc, const float* __restrict__ adst) {
    const int tid = threadIdx.x;
    const int wid = tid >> 5, lane = tid & 31;
    const int wm = (wid & 3) * 32;
    const int wn = (wid >> 2) * 32;
    const int NT = ((FOUT - wn) >= 32) ? 4 : ((FOUT - wn) >> 3);  // active n-tiles
    const int r = lane >> 2;
    const int cc = (lane & 3) * 2;
    const int rowBase = blockIdx.x * 128;

    // A row pointers (clamped; OOB rows discarded at store)
    const __nv_bfloat16* pa[4];
    int rows[4];
#pragma unroll
    for (int m = 0; m < 2; m++) {
        int ra = rowBase + wm + m * 16 + r;
        int rb = ra + 8;
        rows[2 * m] = ra; rows[2 * m + 1] = rb;
        pa[2 * m]     = A3 + (size_t)(ra < NN ? ra : NN - 1) * K3 + cc;
        pa[2 * m + 1] = A3 + (size_t)(rb < NN ? rb : NN - 1) * K3 + cc;
    }
    // B row pointers per n-tile (inactive tiles -> row 0, results discarded)
    const __nv_bfloat16* pb[4];
#pragma unroll
    for (int t = 0; t < 4; t++) {
        int n = wn + t * 8 + r;
        pb[t] = B3 + (size_t)(t < NT ? n : 0) * K3 + cc;
    }

    float acc[2][4][4] = {};

#pragma unroll 4
    for (int k = 0; k < K3; k += 16) {
        uint32_t b[4][2];
#pragma unroll
        for (int t = 0; t < 4; t++) {
            b[t][0] = *(const uint32_t*)(pb[t] + k);
            b[t][1] = *(const uint32_t*)(pb[t] + k + 8);
        }
#pragma unroll
        for (int m = 0; m < 2; m++) {
            uint32_t a[4];
            a[0] = *(const uint32_t*)(pa[2 * m] + k);
            a[1] = *(const uint32_t*)(pa[2 * m + 1] + k);
            a[2] = *(const uint32_t*)(pa[2 * m] + k + 8);
            a[3] = *(const uint32_t*)(pa[2 * m + 1] + k + 8);
#pragma unroll
            for (int t = 0; t < 4; t++)
                mma16816(acc[m][t], a, b[t]);
        }
    }

    // epilogue: store fp32 C + (optionally) fused alpha logits
#pragma unroll
    for (int m = 0; m < 2; m++) {
        int ra = rows[2 * m], rb = rows[2 * m + 1];
#pragma unroll
        for (int t = 0; t < 4; t++) {
            if (t < NT) {
                int n = wn + t * 8 + cc;
                if (ra < NN) *(float2*)(C + (size_t)ra * FOUT + n) =
                    make_float2(acc[m][t][0], acc[m][t][1]);
                if (rb < NN) *(float2*)(C + (size_t)rb * FOUT + n) =
                    make_float2(acc[m][t][2], acc[m][t][3]);
            }
        }
        if (ALPHA) {
            // heads of this warp: h0 = wn/16, h0+1 (16 cols each; t=0,1 -> h0, t=2,3 -> h0+1)
            float p[2][2][2] = {};  // [row ra/rb][head sel][src/dst]
#pragma unroll
            for (int t = 0; t < 4; t++) {
                int hsel = t >> 1;
#pragma unroll
                for (int j = 0; j < 2; j++) {
                    int col = wn + t * 8 + cc + j;
                    float as_v = __ldg(asrc + col);
                    float ad_v = __ldg(adst + col);
                    p[0][hsel][0] += acc[m][t][j] * as_v;
                    p[0][hsel][1] += acc[m][t][j] * ad_v;
                    p[1][hsel][0] += acc[m][t][2 + j] * as_v;
                    p[1][hsel][1] += acc[m][t][2 + j] * ad_v;
                }
            }
#pragma unroll
            for (int i = 0; i < 2; i++)
#pragma unroll
                for (int hsel = 0; hsel < 2; hsel++)
#pragma unroll
                    for (int v = 0; v < 2; v++) {
                        p[i][hsel][v] += __shfl_xor_sync(0xffffffffu, p[i][hsel][v], 1);
                        p[i][hsel][v] += __shfl_xor_sync(0xffffffffu, p[i][hsel][v], 2);
                    }
            if ((lane & 3) == 0) {
                int h0 = wn >> 4;
                if (ra < NN) {
                    g_as[ra * 4 + h0] = p[0][0][0];     g_ad[ra * 4 + h0] = p[0][0][1];
                    g_as[ra * 4 + h0 + 1] = p[0][1][0]; g_ad[ra * 4 + h0 + 1] = p[0][1][1];
                }
                if (rb < NN) {
                    g_as[rb * 4 + h0] = p[1][0][0];     g_ad[rb * 4 + h0] = p[1][0][1];
                    g_as[rb * 4 + h0 + 1] = p[1][1][0]; g_ad[rb * 4 + h0 + 1] = p[1][1][1];
                }
            }
        }
    }
}

// ---------------- CSR construction ----------------
__global__ void hist_kernel(const int* __restrict__ dsts) {
    int e = blockIdx.x * blockDim.x + threadIdx.x;
    if (e >= ETOT) return;
    int d = (e < EE) ? __ldg(dsts + e) : (e - EE);
    atomicAdd(&g_deg[d], 1);
}

__global__ void scan_kernel() {
    __shared__ int sums[1024];
    const int t = threadIdx.x;
    constexpr int CH = (NN + 1 + 1023) / 1024;
    const int base = t * CH;
    int s = 0;
    for (int j = 0; j < CH; j++) {
        int idx = base + j;
        if (idx < NN) s += g_deg[idx];
    }
    sums[t] = s;
    __syncthreads();
    for (int off = 1; off < 1024; off <<= 1) {
        int v = (t >= off) ? sums[t - off] : 0;
        __syncthreads();
        sums[t] += v;
        __syncthreads();
    }
    int run = (t == 0) ? 0 : sums[t - 1];
    for (int j = 0; j < CH; j++) {
        int idx = base + j;
        if (idx <= NN) {
            g_rowptr[idx] = run;
            if (idx < NN) {
                g_cursor[idx] = run;
                run += g_deg[idx];
            }
        }
    }
}

__global__ void fill_kernel(const int* __restrict__ srcs, const int* __restrict__ dsts) {
    int e = blockIdx.x * blockDim.x + threadIdx.x;
    if (e >= ETOT) return;
    int s, d;
    if (e < EE) { s = __ldg(srcs + e); d = __ldg(dsts + e); }
    else        { s = d = e - EE; }
    int pos = atomicAdd(&g_cursor[d], 1);
    g_csr[pos] = s;
}

// ---------------- prep (layer 3): attention logits ----------------
__global__ void prep40_kernel(const float* __restrict__ h,
                              const float* __restrict__ a_src,
                              const float* __restrict__ a_dst) {
    int n = blockIdx.x * blockDim.x + threadIdx.x;
    if (n >= NN) return;
    const float* hp = h + (size_t)n * 40;
    float s1 = 0.f, s2 = 0.f;
#pragma unroll
    for (int c = 0; c < 40; c++) {
        float v = hp[c];
        s1 += v * __ldg(a_src + c);
        s2 += v * __ldg(a_dst + c);
    }
    g_as[n] = s1;
    g_ad[n] = s2;
}

// ---------------- aggregate (layers 1-2): relu + bf16 triple out ----------------
__global__ void agg_mid_kernel(const float* __restrict__ h, const float* __restrict__ bias) {
    int gt = blockIdx.x * blockDim.x + threadIdx.x;
    int n = gt >> 4;
    int q = gt & 15;
    if (n >= NN) return;
    int hh = q >> 2;

    const float ad = g_ad[n * 4 + hh];
    const int beg = __ldg(g_rowptr + n);
    const int end = __ldg(g_rowptr + n + 1);

    float4 acc = make_float4(0.f, 0.f, 0.f, 0.f);
    float den = 0.f;
    for (int i = beg; i < end; i++) {
        int s = __ldg(g_csr + i);
        float v = __ldg(g_as + s * 4 + hh) + ad;
        v = v > 0.f ? v : 0.2f * v;
        float w = __expf(v);
        den += w;
        float4 x = __ldg((const float4*)(h + (size_t)s * 64) + q);
        acc.x += w * x.x; acc.y += w * x.y; acc.z += w * x.z; acc.w += w * x.w;
    }
    float inv = 1.f / (den + 1e-16f);
    float4 b = __ldg((const float4*)bias + q);
    float o[4];
    o[0] = acc.x * inv + b.x; o[1] = acc.y * inv + b.y;
    o[2] = acc.z * inv + b.z; o[3] = acc.w * inv + b.w;
    union { unsigned short s[12]; uint2 u2[3]; } u;
#pragma unroll
    for (int j = 0; j < 4; j++) {
        float rr = o[j] > 0.f ? o[j] : 0.f;
        unsigned short hB, lB;
        split3(rr, hB, lB);
        u.s[3 * j] = hB; u.s[3 * j + 1] = lB; u.s[3 * j + 2] = hB;
    }
    uint2* out = (uint2*)((char*)g_f3 + (size_t)n * 384 + q * 24);
    out[0] = u.u2[0]; out[1] = u.u2[1]; out[2] = u.u2[2];
}

// ---------------- aggregate (layer 3): fp32 output ----------------
__global__ void agg_out_kernel(const float* __restrict__ h, const float* __restrict__ bias,
                               float* __restrict__ dest) {
    int gt = blockIdx.x * blockDim.x + threadIdx.x;
    int n = gt >> 4;
    int q = gt & 15;
    if (n >= NN) return;

    const float ad = g_ad[n];
    const int beg = __ldg(g_rowptr + n);
    const int end = __ldg(g_rowptr + n + 1);

    float4 acc = make_float4(0.f, 0.f, 0.f, 0.f);
    float den = 0.f;
    for (int i = beg; i < end; i++) {
        int s = __ldg(g_csr + i);
        float v = __ldg(g_as + s) + ad;
        v = v > 0.f ? v : 0.2f * v;
        float w = __expf(v);
        den += w;
        if (q < 10) {
            float4 x = __ldg((const float4*)(h + (size_t)s * 40) + q);
            acc.x += w * x.x; acc.y += w * x.y; acc.z += w * x.z; acc.w += w * x.w;
        }
    }
    if (q < 10) {
        float inv = 1.f / (den + 1e-16f);
        float4 b = __ldg((const float4*)bias + q);
        float4 o;
        o.x = acc.x * inv + b.x; o.y = acc.y * inv + b.y;
        o.z = acc.z * inv + b.z; o.w = acc.w * inv + b.w;
        *(float4*)(dest + (size_t)n * 40 + q * 4) = o;
    }
}

// ---------------- launch ----------------
extern "C" void kernel_launch(void* const* d_in, const int* in_sizes, int n_in,
                              void* d_out, int out_size) {
    const float* x = (const float*)d_in[0];
    const int* ei = (const int*)d_in[1];
    const float* W1 = (const float*)d_in[2];
    const float* asr1 = (const float*)d_in[3];
    const float* adr1 = (const float*)d_in[4];
    const float* b1 = (const float*)d_in[5];
    const float* W2 = (const float*)d_in[6];
    const float* asr2 = (const float*)d_in[7];
    const float* adr2 = (const float*)d_in[8];
    const float* b2 = (const float*)d_in[9];
    const float* W3 = (const float*)d_in[10];
    const float* asr3 = (const float*)d_in[11];
    const float* adr3 = (const float*)d_in[12];
    const float* b3 = (const float*)d_in[13];
    float* out = (float*)d_out;

    const int* esrc = ei;
    const int* edst = ei + EE;

    float* p_h;
    void *p_deg, *p_a3, *p_f3, *p_b31, *p_b32, *p_b33;
    cudaGetSymbolAddress((void**)&p_h, g_h);
    cudaGetSymbolAddress(&p_deg, g_deg);
    cudaGetSymbolAddress(&p_a3, g_a3);
    cudaGetSymbolAddress(&p_f3, g_f3);
    cudaGetSymbolAddress(&p_b31, g_b31);
    cudaGetSymbolAddress(&p_b32, g_b32);
    cudaGetSymbolAddress(&p_b33, g_b33);

    const int mmaGrid = (NN + 127) / 128;  // 391
    const int edgeGrid = (ETOT + 255) / 256;
    const int aggGrid = (NN * 16 + 255) / 256;

    // Fork: CSR build on a side stream.
    cudaStream_t s2;
    cudaStreamCreateWithFlags(&s2, cudaStreamNonBlocking);
    cudaEvent_t evFork, evJoin;
    cudaEventCreateWithFlags(&evFork, cudaEventDisableTiming);
    cudaEventCreateWithFlags(&evJoin, cudaEventDisableTiming);

    cudaEventRecord(evFork, 0);
    cudaStreamWaitEvent(s2, evFork, 0);
    cudaMemsetAsync(p_deg, 0, NN * sizeof(int), s2);
    hist_kernel<<<edgeGrid, 256, 0, s2>>>(edst);
    scan_kernel<<<1, 1024, 0, s2>>>();
    fill_kernel<<<edgeGrid, 256, 0, s2>>>(esrc, edst);
    cudaEventRecord(evJoin, s2);

    // conversions
    x3_kernel<<<(NN * 32 + 255) / 256, 256>>>(x);
    w3_kernel<256, 64><<<(256 * 64 + 255) / 256, 256>>>(W1, (__nv_bfloat16*)p_b31);
    w3_kernel<64, 64><<<(64 * 64 + 255) / 256, 256>>>(W2, (__nv_bfloat16*)p_b32);
    w3_kernel<64, 40><<<(64 * 40 + 255) / 256, 256>>>(W3, (__nv_bfloat16*)p_b33);

    // ---------------- layer 1 ----------------
    mma_gemm<768, 64, true><<<mmaGrid, 256>>>(
        (const __nv_bfloat16*)p_a3, (const __nv_bfloat16*)p_b31, p_h, asr1, adr1);
    cudaStreamWaitEvent(0, evJoin, 0);
    agg_mid_kernel<<<aggGrid, 256>>>(p_h, b1);

    // ---------------- layer 2 ----------------
    mma_gemm<192, 64, true><<<mmaGrid, 256>>>(
        (const __nv_bfloat16*)p_f3, (const __nv_bfloat16*)p_b32, p_h, asr2, adr2);
    agg_mid_kernel<<<aggGrid, 256>>>(p_h, b2);

    // ---------------- layer 3 ----------------
    mma_gemm<192, 40, false><<<mmaGrid, 256>>>(
        (const __nv_bfloat16*)p_f3, (const __nv_bfloat16*)p_b33, p_h, nullptr, nullptr);
    prep40_kernel<<<(NN + 255) / 256, 256>>>(p_h, asr3, adr3);
    agg_out_kernel<<<aggGrid, 256>>>(p_h, b3, out);
}

// round 12
// speedup vs baseline: 1.1010x; 1.1010x over previous
#include <cuda_runtime.h>
#include <cuda_fp16.h>
#include <math.h>
#include <stdint.h>

#define NN 50000
#define EE 800000
#define ETOT (EE + NN)

// ---------------- device scratch ----------------
__device__ __align__(16) __half g_h[NN * 64];    // pre-attention features (fp16 gather payload)
__device__ __align__(16) float g_feat[NN * 64];  // layer output -> next GEMM input (fp32)
__device__ __align__(16) float g_as[NN * 4];
__device__ __align__(16) float g_ad[NN * 4];
__device__ int g_deg[NN];
__device__ int g_rowptr[NN + 1];
__device__ int g_cursor[NN];
__device__ int g_csr[ETOT];

// ---------------- packed f32x2 helpers ----------------
__device__ __forceinline__ void ffma2(unsigned long long& acc, unsigned long long a,
                                      unsigned long long b) {
    asm("fma.rn.f32x2 %0, %1, %2, %0;" : "+l"(acc) : "l"(a), "l"(b));
}
__device__ __forceinline__ unsigned long long bcast2(float x) {
    unsigned long long r;
    asm("mov.b64 %0, {%1, %1};" : "=l"(r) : "f"(x));
    return r;
}
__device__ __forceinline__ float2 unpack2(unsigned long long p) {
    float2 f;
    asm("mov.b64 {%0, %1}, %2;" : "=f"(f.x), "=f"(f.y) : "l"(p));
    return f;
}

// ---------------- GEMM: C[n, FOUT](fp16) = X[n, FIN](fp32) * W[FIN, FOUT] ----------------
// TM=64 rows/block, 4 rows x 4 cols per thread, blockDim = CG*16, minBlocks=3. (R8 shape)
template <int FIN, int FOUT, int TK, bool ALPHA>
__global__ void __launch_bounds__((FOUT / 4) * 16, 3) gemm_kernel(
    const float* __restrict__ X, const float* __restrict__ W,
    __half* __restrict__ C, const float* __restrict__ asrc,
    const float* __restrict__ adst, int nrows) {
    constexpr int CG = FOUT / 4;
    constexpr int TM = 64;
    constexpr int XPITCH = TK + 4;
    constexpr int NT = CG * 16;
    extern __shared__ float smem[];
    float* Xs = smem;
    float* Ws = smem + TM * XPITCH;

    const int tid = threadIdx.x;
    const int cg = tid % CG;
    const int rg = tid / CG;
    const int rowBase = blockIdx.x * TM;

    float a_s[4], a_d[4];
    if (ALPHA) {
#pragma unroll
        for (int j = 0; j < 4; j++) {
            a_s[j] = __ldg(asrc + cg * 4 + j);
            a_d[j] = __ldg(adst + cg * 4 + j);
        }
    }

    unsigned long long acc01[4], acc23[4];
#pragma unroll
    for (int i = 0; i < 4; i++) { acc01[i] = 0ull; acc23[i] = 0ull; }

    for (int k0 = 0; k0 < FIN; k0 += TK) {
        __syncthreads();
        for (int idx = tid; idx < TM * (TK / 4); idx += NT) {
            int r = idx / (TK / 4);
            int k4 = idx % (TK / 4);
            float4 v = make_float4(0.f, 0.f, 0.f, 0.f);
            int row = rowBase + r;
            if (row < nrows)
                v = *(const float4*)(X + (size_t)row * FIN + k0 + k4 * 4);
            *(float4*)(Xs + r * XPITCH + k4 * 4) = v;
        }
        for (int idx = tid; idx < TK * CG; idx += NT) {
            int k = idx / CG;
            int c4 = idx % CG;
            *(float4*)(Ws + k * FOUT + c4 * 4) =
                *(const float4*)(W + (size_t)(k0 + k) * FOUT + c4 * 4);
        }
        __syncthreads();

        for (int k4 = 0; k4 < TK / 4; k4++) {
            float4 xq[4];
#pragma unroll
            for (int i = 0; i < 4; i++)
                xq[i] = *(float4*)(Xs + (rg * 4 + i) * XPITCH + k4 * 4);
#pragma unroll
            for (int kk = 0; kk < 4; kk++) {
                ulonglong2 wv = *(const ulonglong2*)(Ws + (k4 * 4 + kk) * FOUT + cg * 4);
#pragma unroll
                for (int i = 0; i < 4; i++) {
                    float xv = (kk == 0) ? xq[i].x : (kk == 1) ? xq[i].y
                              : (kk == 2) ? xq[i].z : xq[i].w;
                    unsigned long long x2 = bcast2(xv);
                    ffma2(acc01[i], x2, wv.x);
                    ffma2(acc23[i], x2, wv.y);
                }
            }
        }
    }

#pragma unroll
    for (int i = 0; i < 4; i++) {
        int row = rowBase + rg * 4 + i;
        float2 lo = unpack2(acc01[i]);
        float2 hi = unpack2(acc23[i]);
        if (row < nrows) {
            // fp16 store: 4 cols = 8 bytes
            __half2 p0 = __floats2half2_rn(lo.x, lo.y);
            __half2 p1 = __floats2half2_rn(hi.x, hi.y);
            uint2 u = make_uint2(*(uint32_t*)&p0, *(uint32_t*)&p1);
            *(uint2*)(C + (size_t)row * FOUT + cg * 4) = u;
        }
        if (ALPHA) {
            float p1d = lo.x * a_s[0] + lo.y * a_s[1] + hi.x * a_s[2] + hi.y * a_s[3];
            float p2d = lo.x * a_d[0] + lo.y * a_d[1] + hi.x * a_d[2] + hi.y * a_d[3];
            p1d += __shfl_xor_sync(0xffffffffu, p1d, 1);
            p1d += __shfl_xor_sync(0xffffffffu, p1d, 2);
            p2d += __shfl_xor_sync(0xffffffffu, p2d, 1);
            p2d += __shfl_xor_sync(0xffffffffu, p2d, 2);
            if ((cg & 3) == 0 && row < nrows) {
                g_as[row * 4 + (cg >> 2)] = p1d;
                g_ad[row * 4 + (cg >> 2)] = p2d;
            }
        }
    }
}

// ---------------- CSR construction ----------------
__global__ void hist_kernel(const int* __restrict__ dsts) {
    int e = blockIdx.x * blockDim.x + threadIdx.x;
    if (e >= ETOT) return;
    int d = (e < EE) ? __ldg(dsts + e) : (e - EE);
    atomicAdd(&g_deg[d], 1);
}

__global__ void scan_kernel() {
    __shared__ int sums[1024];
    const int t = threadIdx.x;
    constexpr int CH = (NN + 1 + 1023) / 1024;
    const int base = t * CH;
    int s = 0;
    for (int j = 0; j < CH; j++) {
        int idx = base + j;
        if (idx < NN) s += g_deg[idx];
    }
    sums[t] = s;
    __syncthreads();
    for (int off = 1; off < 1024; off <<= 1) {
        int v = (t >= off) ? sums[t - off] : 0;
        __syncthreads();
        sums[t] += v;
        __syncthreads();
    }
    int run = (t == 0) ? 0 : sums[t - 1];
    for (int j = 0; j < CH; j++) {
        int idx = base + j;
        if (idx <= NN) {
            g_rowptr[idx] = run;
            if (idx < NN) {
                g_cursor[idx] = run;
                run += g_deg[idx];
            }
        }
    }
}

__global__ void fill_kernel(const int* __restrict__ srcs, const int* __restrict__ dsts) {
    int e = blockIdx.x * blockDim.x + threadIdx.x;
    if (e >= ETOT) return;
    int s, d;
    if (e < EE) { s = __ldg(srcs + e); d = __ldg(dsts + e); }
    else        { s = d = e - EE; }
    int pos = atomicAdd(&g_cursor[d], 1);
    g_csr[pos] = s;
}

// ---------------- prep (layer 3): attention logits from fp16 h ----------------
__global__ void prep40_kernel(const __half* __restrict__ h,
                              const float* __restrict__ a_src,
                              const float* __restrict__ a_dst) {
    int n = blockIdx.x * blockDim.x + threadIdx.x;
    if (n >= NN) return;
    const __half* hp = h + (size_t)n * 40;
    float s1 = 0.f, s2 = 0.f;
#pragma unroll
    for (int c = 0; c < 40; c++) {
        float v = __half2float(hp[c]);
        s1 += v * __ldg(a_src + c);
        s2 += v * __ldg(a_dst + c);
    }
    g_as[n] = s1;
    g_ad[n] = s2;
}

// ---------------- aggregate (layers 1-2): fp16 gather, fp32 out + relu ----------------
__global__ void agg_mid_kernel(const __half* __restrict__ h, const float* __restrict__ bias,
                               float* __restrict__ dest) {
    int gt = blockIdx.x * blockDim.x + threadIdx.x;
    int n = gt >> 4;
    int q = gt & 15;
    if (n >= NN) return;
    int hh = q >> 2;

    const float ad = g_ad[n * 4 + hh];
    const int beg = __ldg(g_rowptr + n);
    const int end = __ldg(g_rowptr + n + 1);

    float4 acc = make_float4(0.f, 0.f, 0.f, 0.f);
    float den = 0.f;
    for (int i = beg; i < end; i++) {
        int s = __ldg(g_csr + i);
        float v = __ldg(g_as + s * 4 + hh) + ad;
        v = v > 0.f ? v : 0.2f * v;
        float w = __expf(v);
        den += w;
        uint2 u = __ldg((const uint2*)(h + (size_t)s * 64) + q);
        float2 f01 = __half22float2(*(__half2*)&u.x);
        float2 f23 = __half22float2(*(__half2*)&u.y);
        acc.x += w * f01.x; acc.y += w * f01.y;
        acc.z += w * f23.x; acc.w += w * f23.y;
    }
    float inv = 1.f / (den + 1e-16f);
    float4 b = __ldg((const float4*)bias + q);
    float4 o;
    o.x = acc.x * inv + b.x; o.y = acc.y * inv + b.y;
    o.z = acc.z * inv + b.z; o.w = acc.w * inv + b.w;
    o.x = o.x > 0.f ? o.x : 0.f;
    o.y = o.y > 0.f ? o.y : 0.f;
    o.z = o.z > 0.f ? o.z : 0.f;
    o.w = o.w > 0.f ? o.w : 0.f;
    *(float4*)(dest + (size_t)n * 64 + q * 4) = o;
}

// ---------------- aggregate (layer 3): fp16 gather, fp32 out ----------------
__global__ void agg_out_kernel(const __half* __restrict__ h, const float* __restrict__ bias,
                               float* __restrict__ dest) {
    int gt = blockIdx.x * blockDim.x + threadIdx.x;
    int n = gt >> 4;
    int q = gt & 15;
    if (n >= NN) return;

    const float ad = g_ad[n];
    const int beg = __ldg(g_rowptr + n);
    const int end = __ldg(g_rowptr + n + 1);

    float4 acc = make_float4(0.f, 0.f, 0.f, 0.f);
    float den = 0.f;
    for (int i = beg; i < end; i++) {
        int s = __ldg(g_csr + i);
        float v = __ldg(g_as + s) + ad;
        v = v > 0.f ? v : 0.2f * v;
        float w = __expf(v);
        den += w;
        if (q < 10) {
            uint2 u = __ldg((const uint2*)(h + (size_t)s * 40) + q);
            float2 f01 = __half22float2(*(__half2*)&u.x);
            float2 f23 = __half22float2(*(__half2*)&u.y);
            acc.x += w * f01.x; acc.y += w * f01.y;
            acc.z += w * f23.x; acc.w += w * f23.y;
        }
    }
    if (q < 10) {
        float inv = 1.f / (den + 1e-16f);
        float4 b = __ldg((const float4*)bias + q);
        float4 o;
        o.x = acc.x * inv + b.x; o.y = acc.y * inv + b.y;
        o.z = acc.z * inv + b.z; o.w = acc.w * inv + b.w;
        *(float4*)(dest + (size_t)n * 40 + q * 4) = o;
    }
}

// ---------------- launch ----------------
extern "C" void kernel_launch(void* const* d_in, const int* in_sizes, int n_in,
                              void* d_out, int out_size) {
    const float* x = (const float*)d_in[0];
    const int* ei = (const int*)d_in[1];    // int32 (JAX x64 disabled)
    const float* W1 = (const float*)d_in[2];
    const float* asr1 = (const float*)d_in[3];
    const float* adr1 = (const float*)d_in[4];
    const float* b1 = (const float*)d_in[5];
    const float* W2 = (const float*)d_in[6];
    const float* asr2 = (const float*)d_in[7];
    const float* adr2 = (const float*)d_in[8];
    const float* b2 = (const float*)d_in[9];
    const float* W3 = (const float*)d_in[10];
    const float* asr3 = (const float*)d_in[11];
    const float* adr3 = (const float*)d_in[12];
    const float* b3 = (const float*)d_in[13];
    float* out = (float*)d_out;

    const int* esrc = ei;
    const int* edst = ei + EE;

    __half* p_h;
    float* p_feat;
    void* p_deg;
    cudaGetSymbolAddress((void**)&p_h, g_h);
    cudaGetSymbolAddress((void**)&p_feat, g_feat);
    cudaGetSymbolAddress(&p_deg, g_deg);

    constexpr int SMEM64 = (64 * (64 + 4) + 64 * 64) * 4;  // 33792
    constexpr int SMEM40 = (64 * (64 + 4) + 64 * 40) * 4;  // 27648

    const int gemmGrid = (NN + 63) / 64;   // 782
    const int edgeGrid = (ETOT + 255) / 256;
    const int aggGrid = (NN * 16 + 255) / 256;

    // Fork: CSR build on a side stream, overlapped with layer-1 GEMM.
    cudaStream_t s2;
    cudaStreamCreateWithFlags(&s2, cudaStreamNonBlocking);
    cudaEvent_t evFork, evJoin;
    cudaEventCreateWithFlags(&evFork, cudaEventDisableTiming);
    cudaEventCreateWithFlags(&evJoin, cudaEventDisableTiming);

    cudaEventRecord(evFork, 0);
    cudaStreamWaitEvent(s2, evFork, 0);
    cudaMemsetAsync(p_deg, 0, NN * sizeof(int), s2);
    hist_kernel<<<edgeGrid, 256, 0, s2>>>(edst);
    scan_kernel<<<1, 1024, 0, s2>>>();
    fill_kernel<<<edgeGrid, 256, 0, s2>>>(esrc, edst);
    cudaEventRecord(evJoin, s2);

    // ---------------- layer 1: 256 -> 4x16 ----------------
    gemm_kernel<256, 64, 64, true><<<gemmGrid, 256, SMEM64>>>(x, W1, p_h, asr1, adr1, NN);
    cudaStreamWaitEvent(0, evJoin, 0);
    agg_mid_kernel<<<aggGrid, 256>>>(p_h, b1, p_feat);

    // ---------------- layer 2: 64 -> 4x16 ----------------
    gemm_kernel<64, 64, 64, true><<<gemmGrid, 256, SMEM64>>>(p_feat, W2, p_h, asr2, adr2, NN);
    agg_mid_kernel<<<aggGrid, 256>>>(p_h, b2, p_feat);

    // ---------------- layer 3: 64 -> 1x40 ----------------
    gemm_kernel<64, 40, 64, false><<<gemmGrid, 160, SMEM40>>>(p_feat, W3, p_h, nullptr, nullptr, NN);
    prep40_kernel<<<(NN + 255) / 256, 256>>>(p_h, asr3, adr3);
    agg_out_kernel<<<aggGrid, 256>>>(p_h, b3, out);
}

// round 13
// speedup vs baseline: 1.3564x; 1.2320x over previous
#include <cuda_runtime.h>
#include <cuda_fp16.h>
#include <cuda_bf16.h>
#include <math.h>
#include <stdint.h>

#define NN 50000
#define EE 800000
#define ETOT (EE + NN)

// ---------------- device scratch ----------------
__device__ __align__(16) __half g_h[NN * 64];    // pre-attention features (fp16 gather payload)
__device__ __align__(16) float g_feat[NN * 64];  // layer output -> next GEMM input (fp32)
__device__ __align__(16) float g_as[NN * 4];
__device__ __align__(16) float g_ad[NN * 4];
__device__ int g_deg[NN];
__device__ int g_rowptr[NN + 1];
__device__ int g_cursor[NN];
__device__ int g_csr[ETOT];

// ---------------- fp32 -> bf16 split ----------------
__device__ __forceinline__ void split3(float x, unsigned short& h, unsigned short& l) {
    __nv_bfloat16 hb = __float2bfloat16(x);
    float lo = x - __bfloat162float(hb);
    __nv_bfloat16 lb = __float2bfloat16(lo);
    h = *(unsigned short*)&hb;
    l = *(unsigned short*)&lb;
}

__device__ __forceinline__ void mma16816(float* c, const uint32_t* a, const uint32_t* b) {
    asm volatile(
        "mma.sync.aligned.m16n8k16.row.col.f32.bf16.bf16.f32 "
        "{%0,%1,%2,%3}, {%4,%5,%6,%7}, {%8,%9}, {%0,%1,%2,%3};"
        : "+f"(c[0]), "+f"(c[1]), "+f"(c[2]), "+f"(c[3])
        : "r"(a[0]), "r"(a[1]), "r"(a[2]), "r"(a[3]), "r"(b[0]), "r"(b[1]));
}

// ---------------- tensor GEMM: C[n,FOUT](fp16) = X[n,FIN](fp32) @ W[FIN,FOUT] ----------------
// In-kernel bf16 triple split: A=[xh,xl,xh], B=[wh,wh,wl] -> only xl*wl (~2^-18) dropped.
// 128 rows/block, 8 warps, warp w owns m-tile w (16 rows), loops all n-tiles.
// PITCH=104 elems (52 words/row): bank = (20*r + c)%32, conflict-free fragment LDS.
template <int FIN, int FOUT, bool ALPHA>
__global__ void __launch_bounds__(256) mma_gemm(
    const float* __restrict__ X, const float* __restrict__ W,
    __half* __restrict__ C, const float* __restrict__ asrc,
    const float* __restrict__ adst) {
    constexpr int KC = 32;             // fp32 K per chunk
    constexpr int NCH = FIN / KC;      // 8 or 2
    constexpr int PITCH = 104;         // bf16 elems per smem row (96 used)
    constexpr int NT = FOUT / 8;       // 8 or 5

    __shared__ unsigned short As[128 * PITCH];
    __shared__ unsigned short Bs[FOUT * PITCH];

    const int tid = threadIdx.x;
    const int wid = tid >> 5, lane = tid & 31;
    const int r4 = lane >> 2;          // 0..7
    const int c2 = (lane & 3) * 2;     // 0,2,4,6
    const int rowBase = blockIdx.x * 128;
    const int wm = wid * 16;

    float acc[NT][4];
#pragma unroll
    for (int t = 0; t < NT; t++)
#pragma unroll
        for (int j = 0; j < 4; j++) acc[t][j] = 0.f;

    for (int ch = 0; ch < NCH; ch++) {
        __syncthreads();
        // ---- stage A tile: 128 x 32 fp32 -> 128 x 96 bf16 triple ----
        for (int idx = tid; idx < 128 * (KC / 4); idx += 256) {
            int r = idx >> 3, c4 = idx & 7;
            int row = rowBase + r;
            float4 v = make_float4(0.f, 0.f, 0.f, 0.f);
            if (row < NN) v = *(const float4*)(X + (size_t)row * FIN + ch * KC + c4 * 4);
            unsigned short* ap = As + r * PITCH + 12 * c4;
            float vv[4] = {v.x, v.y, v.z, v.w};
#pragma unroll
            for (int j = 0; j < 4; j++) {
                unsigned short h, l;
                split3(vv[j], h, l);
                ap[3 * j] = h; ap[3 * j + 1] = l; ap[3 * j + 2] = h;
            }
        }
        // ---- stage B tile: 32 x FOUT fp32 -> FOUT x 96 bf16 triple (transposed) ----
        for (int idx = tid; idx < KC * FOUT; idx += 256) {
            int k = idx / FOUT, n = idx % FOUT;
            unsigned short h, l;
            split3(__ldg(W + (size_t)(ch * KC + k) * FOUT + n), h, l);
            unsigned short* bp = Bs + n * PITCH + 3 * k;
            bp[0] = h; bp[1] = h; bp[2] = l;
        }
        __syncthreads();

        // ---- MMA over 96 bf16 = 6 k-steps of 16 ----
#pragma unroll
        for (int ks = 0; ks < 6; ks++) {
            int kb = ks * 16 + c2;
            uint32_t a[4];
            a[0] = *(const uint32_t*)(As + (wm + r4) * PITCH + kb);
            a[1] = *(const uint32_t*)(As + (wm + r4 + 8) * PITCH + kb);
            a[2] = *(const uint32_t*)(As + (wm + r4) * PITCH + kb + 8);
            a[3] = *(const uint32_t*)(As + (wm + r4 + 8) * PITCH + kb + 8);
#pragma unroll
            for (int t = 0; t < NT; t++) {
                uint32_t b[2];
                b[0] = *(const uint32_t*)(Bs + (t * 8 + r4) * PITCH + kb);
                b[1] = *(const uint32_t*)(Bs + (t * 8 + r4) * PITCH + kb + 8);
                mma16816(acc[t], a, b);
            }
        }
    }

    // ---- epilogue: fp16 C stores + fused alpha logits ----
    int ra = rowBase + wm + r4;
    int rb = ra + 8;
#pragma unroll
    for (int t = 0; t < NT; t++) {
        int col = t * 8 + c2;
        if (ra < NN) {
            __half2 p = __floats2half2_rn(acc[t][0], acc[t][1]);
            *(__half2*)(C + (size_t)ra * FOUT + col) = p;
        }
        if (rb < NN) {
            __half2 p = __floats2half2_rn(acc[t][2], acc[t][3]);
            *(__half2*)(C + (size_t)rb * FOUT + col) = p;
        }
    }
    if (ALPHA) {
        // heads: 16 cols each; n-tiles 2h, 2h+1 -> head h
#pragma unroll
        for (int h = 0; h < 4; h++) {
            float pa_s = 0.f, pa_d = 0.f, pb_s = 0.f, pb_d = 0.f;
#pragma unroll
            for (int tt = 0; tt < 2; tt++) {
                int t = 2 * h + tt;
#pragma unroll
                for (int j = 0; j < 2; j++) {
                    int col = t * 8 + c2 + j;
                    float as_v = __ldg(asrc + col);
                    float ad_v = __ldg(adst + col);
                    pa_s += acc[t][j] * as_v;     pa_d += acc[t][j] * ad_v;
                    pb_s += acc[t][2 + j] * as_v; pb_d += acc[t][2 + j] * ad_v;
                }
            }
            pa_s += __shfl_xor_sync(0xffffffffu, pa_s, 1);
            pa_s += __shfl_xor_sync(0xffffffffu, pa_s, 2);
            pa_d += __shfl_xor_sync(0xffffffffu, pa_d, 1);
            pa_d += __shfl_xor_sync(0xffffffffu, pa_d, 2);
            pb_s += __shfl_xor_sync(0xffffffffu, pb_s, 1);
            pb_s += __shfl_xor_sync(0xffffffffu, pb_s, 2);
            pb_d += __shfl_xor_sync(0xffffffffu, pb_d, 1);
            pb_d += __shfl_xor_sync(0xffffffffu, pb_d, 2);
            if ((lane & 3) == 0) {
                if (ra < NN) { g_as[ra * 4 + h] = pa_s; g_ad[ra * 4 + h] = pa_d; }
                if (rb < NN) { g_as[rb * 4 + h] = pb_s; g_ad[rb * 4 + h] = pb_d; }
            }
        }
    }
}

// ---------------- CSR construction ----------------
__global__ void hist_kernel(const int* __restrict__ dsts) {
    int e = blockIdx.x * blockDim.x + threadIdx.x;
    if (e >= ETOT) return;
    int d = (e < EE) ? __ldg(dsts + e) : (e - EE);
    atomicAdd(&g_deg[d], 1);
}

__global__ void scan_kernel() {
    __shared__ int sums[1024];
    const int t = threadIdx.x;
    constexpr int CH = (NN + 1 + 1023) / 1024;
    const int base = t * CH;
    int s = 0;
    for (int j = 0; j < CH; j++) {
        int idx = base + j;
        if (idx < NN) s += g_deg[idx];
    }
    sums[t] = s;
    __syncthreads();
    for (int off = 1; off < 1024; off <<= 1) {
        int v = (t >= off) ? sums[t - off] : 0;
        __syncthreads();
        sums[t] += v;
        __syncthreads();
    }
    int run = (t == 0) ? 0 : sums[t - 1];
    for (int j = 0; j < CH; j++) {
        int idx = base + j;
        if (idx <= NN) {
            g_rowptr[idx] = run;
            if (idx < NN) {
                g_cursor[idx] = run;
                run += g_deg[idx];
            }
        }
    }
}

__global__ void fill_kernel(const int* __restrict__ srcs, const int* __restrict__ dsts) {
    int e = blockIdx.x * blockDim.x + threadIdx.x;
    if (e >= ETOT) return;
    int s, d;
    if (e < EE) { s = __ldg(srcs + e); d = __ldg(dsts + e); }
    else        { s = d = e - EE; }
    int pos = atomicAdd(&g_cursor[d], 1);
    g_csr[pos] = s;
}

// ---------------- prep (layer 3): attention logits from fp16 h ----------------
__global__ void prep40_kernel(const __half* __restrict__ h,
                              const float* __restrict__ a_src,
                              const float* __restrict__ a_dst) {
    int n = blockIdx.x * blockDim.x + threadIdx.x;
    if (n >= NN) return;
    const __half* hp = h + (size_t)n * 40;
    float s1 = 0.f, s2 = 0.f;
#pragma unroll
    for (int c = 0; c < 40; c++) {
        float v = __half2float(hp[c]);
        s1 += v * __ldg(a_src + c);
        s2 += v * __ldg(a_dst + c);
    }
    g_as[n] = s1;
    g_ad[n] = s2;
}

// ---------------- aggregate (layers 1-2): fp16 gather, fp32 out + relu ----------------
__global__ void agg_mid_kernel(const __half* __restrict__ h, const float* __restrict__ bias,
                               float* __restrict__ dest) {
    int gt = blockIdx.x * blockDim.x + threadIdx.x;
    int n = gt >> 4;
    int q = gt & 15;
    if (n >= NN) return;
    int hh = q >> 2;

    const float ad = g_ad[n * 4 + hh];
    const int beg = __ldg(g_rowptr + n);
    const int end = __ldg(g_rowptr + n + 1);

    float4 acc = make_float4(0.f, 0.f, 0.f, 0.f);
    float den = 0.f;
    for (int i = beg; i < end; i++) {
        int s = __ldg(g_csr + i);
        float v = __ldg(g_as + s * 4 + hh) + ad;
        v = v > 0.f ? v : 0.2f * v;
        float w = __expf(v);
        den += w;
        uint2 u = __ldg((const uint2*)(h + (size_t)s * 64) + q);
        float2 f01 = __half22float2(*(__half2*)&u.x);
        float2 f23 = __half22float2(*(__half2*)&u.y);
        acc.x += w * f01.x; acc.y += w * f01.y;
        acc.z += w * f23.x; acc.w += w * f23.y;
    }
    float inv = 1.f / (den + 1e-16f);
    float4 b = __ldg((const float4*)bias + q);
    float4 o;
    o.x = acc.x * inv + b.x; o.y = acc.y * inv + b.y;
    o.z = acc.z * inv + b.z; o.w = acc.w * inv + b.w;
    o.x = o.x > 0.f ? o.x : 0.f;
    o.y = o.y > 0.f ? o.y : 0.f;
    o.z = o.z > 0.f ? o.z : 0.f;
    o.w = o.w > 0.f ? o.w : 0.f;
    *(float4*)(dest + (size_t)n * 64 + q * 4) = o;
}

// ---------------- aggregate (layer 3): fp16 gather, fp32 out ----------------
__global__ void agg_out_kernel(const __half* __restrict__ h, const float* __restrict__ bias,
                               float* __restrict__ dest) {
    int gt = blockIdx.x * blockDim.x + threadIdx.x;
    int n = gt >> 4;
    int q = gt & 15;
    if (n >= NN) return;

    const float ad = g_ad[n];
    const int beg = __ldg(g_rowptr + n);
    const int end = __ldg(g_rowptr + n + 1);

    float4 acc = make_float4(0.f, 0.f, 0.f, 0.f);
    float den = 0.f;
    for (int i = beg; i < end; i++) {
        int s = __ldg(g_csr + i);
        float v = __ldg(g_as + s) + ad;
        v = v > 0.f ? v : 0.2f * v;
        float w = __expf(v);
        den += w;
        if (q < 10) {
            uint2 u = __ldg((const uint2*)(h + (size_t)s * 40) + q);
            float2 f01 = __half22float2(*(__half2*)&u.x);
            float2 f23 = __half22float2(*(__half2*)&u.y);
            acc.x += w * f01.x; acc.y += w * f01.y;
            acc.z += w * f23.x; acc.w += w * f23.y;
        }
    }
    if (q < 10) {
        float inv = 1.f / (den + 1e-16f);
        float4 b = __ldg((const float4*)bias + q);
        float4 o;
        o.x = acc.x * inv + b.x; o.y = acc.y * inv + b.y;
        o.z = acc.z * inv + b.z; o.w = acc.w * inv + b.w;
        *(float4*)(dest + (size_t)n * 40 + q * 4) = o;
    }
}

// ---------------- launch ----------------
extern "C" void kernel_launch(void* const* d_in, const int* in_sizes, int n_in,
                              void* d_out, int out_size) {
    const float* x = (const float*)d_in[0];
    const int* ei = (const int*)d_in[1];    // int32 (JAX x64 disabled)
    const float* W1 = (const float*)d_in[2];
    const float* asr1 = (const float*)d_in[3];
    const float* adr1 = (const float*)d_in[4];
    const float* b1 = (const float*)d_in[5];
    const float* W2 = (const float*)d_in[6];
    const float* asr2 = (const float*)d_in[7];
    const float* adr2 = (const float*)d_in[8];
    const float* b2 = (const float*)d_in[9];
    const float* W3 = (const float*)d_in[10];
    const float* asr3 = (const float*)d_in[11];
    const float* adr3 = (const float*)d_in[12];
    const float* b3 = (const float*)d_in[13];
    float* out = (float*)d_out;

    const int* esrc = ei;
    const int* edst = ei + EE;

    __half* p_h;
    float* p_feat;
    void* p_deg;
    cudaGetSymbolAddress((void**)&p_h, g_h);
    cudaGetSymbolAddress((void**)&p_feat, g_feat);
    cudaGetSymbolAddress(&p_deg, g_deg);

    const int mmaGrid = (NN + 127) / 128;  // 391
    const int edgeGrid = (ETOT + 255) / 256;
    const int aggGrid = (NN * 16 + 255) / 256;

    // Fork: CSR build on a side stream, overlapped with layer-1 GEMM.
    cudaStream_t s2;
    cudaStreamCreateWithFlags(&s2, cudaStreamNonBlocking);
    cudaEvent_t evFork, evJoin;
    cudaEventCreateWithFlags(&evFork, cudaEventDisableTiming);
    cudaEventCreateWithFlags(&evJoin, cudaEventDisableTiming);

    cudaEventRecord(evFork, 0);
    cudaStreamWaitEvent(s2, evFork, 0);
    cudaMemsetAsync(p_deg, 0, NN * sizeof(int), s2);
    hist_kernel<<<edgeGrid, 256, 0, s2>>>(edst);
    scan_kernel<<<1, 1024, 0, s2>>>();
    fill_kernel<<<edgeGrid, 256, 0, s2>>>(esrc, edst);
    cudaEventRecord(evJoin, s2);

    // ---------------- layer 1: 256 -> 4x16 ----------------
    mma_gemm<256, 64, true><<<mmaGrid, 256>>>(x, W1, p_h, asr1, adr1);
    cudaStreamWaitEvent(0, evJoin, 0);
    agg_mid_kernel<<<aggGrid, 256>>>(p_h, b1, p_feat);

    // ---------------- layer 2: 64 -> 4x16 ----------------
    mma_gemm<64, 64, true><<<mmaGrid, 256>>>(p_feat, W2, p_h, asr2, adr2);
    agg_mid_kernel<<<aggGrid, 256>>>(p_h, b2, p_feat);

    // ---------------- layer 3: 64 -> 1x40 ----------------
    mma_gemm<64, 40, false><<<mmaGrid, 256>>>(p_feat, W3, p_h, nullptr, nullptr);
    prep40_kernel<<<(NN + 255) / 256, 256>>>(p_h, asr3, adr3);
    agg_out_kernel<<<aggGrid, 256>>>(p_h, b3, out);
}

// round 14
// speedup vs baseline: 1.3769x; 1.0151x over previous
#include <cuda_runtime.h>
#include <cuda_fp16.h>
#include <cuda_bf16.h>
#include <math.h>
#include <stdint.h>

#define NN 50000
#define EE 800000
#define ETOT (EE + NN)

// ---------------- device scratch ----------------
__device__ __align__(16) __half g_h[NN * 64];    // pre-attention features (fp16 gather payload)
__device__ __align__(16) float g_feat[NN * 64];  // layer output -> next GEMM input (fp32)
__device__ __align__(16) float g_as[NN * 4];
__device__ __align__(16) float g_ad[NN * 4];
__device__ int g_deg[NN];
__device__ int g_rowptr[NN + 1];
__device__ int g_cursor[NN];
__device__ int g_csr[ETOT];

// ---------------- fp32 -> bf16 split ----------------
__device__ __forceinline__ void split2(float x, unsigned short& h, unsigned short& l) {
    __nv_bfloat16 hb = __float2bfloat16(x);
    float lo = x - __bfloat162float(hb);
    __nv_bfloat16 lb = __float2bfloat16(lo);
    h = *(unsigned short*)&hb;
    l = *(unsigned short*)&lb;
}

__device__ __forceinline__ void mma16816(float* c, const uint32_t* a, const uint32_t* b) {
    asm volatile(
        "mma.sync.aligned.m16n8k16.row.col.f32.bf16.bf16.f32 "
        "{%0,%1,%2,%3}, {%4,%5,%6,%7}, {%8,%9}, {%0,%1,%2,%3};"
        : "+f"(c[0]), "+f"(c[1]), "+f"(c[2]), "+f"(c[3])
        : "r"(a[0]), "r"(a[1]), "r"(a[2]), "r"(a[3]), "r"(b[0]), "r"(b[1]));
}

// ---------------- tensor GEMM: C[n,FOUT](fp16) = X[n,FIN](fp32) @ W[FIN,FOUT] ----------------
// Dual bf16 layout [xh(32) | xl(32)] per 32-fp32 chunk; 3-pass MMA with fragment reuse:
// C += Ah@Bh + Al@Bh + Ah@Bl  (only xl@wl ~2^-18 dropped).
// PITCH=72 elems (36 words): fragment bank = (4r+c)%32, conflict-free.
template <int FIN, int FOUT, bool ALPHA>
__global__ void __launch_bounds__(256, 3) mma_gemm(
    const float* __restrict__ X, const float* __restrict__ W,
    __half* __restrict__ C, const float* __restrict__ asrc,
    const float* __restrict__ adst) {
    constexpr int KC = 32;             // fp32 K per chunk
    constexpr int NCH = FIN / KC;      // 8 or 2
    constexpr int PITCH = 72;          // bf16 elems per smem row (64 used)
    constexpr int NT = FOUT / 8;       // 8 or 5

    __shared__ unsigned short As[128 * PITCH];
    __shared__ unsigned short Bs[FOUT * PITCH];

    const int tid = threadIdx.x;
    const int wid = tid >> 5, lane = tid & 31;
    const int r4 = lane >> 2;          // 0..7
    const int c2 = (lane & 3) * 2;     // 0,2,4,6
    const int rowBase = blockIdx.x * 128;
    const int wm = wid * 16;

    float acc[NT][4];
#pragma unroll
    for (int t = 0; t < NT; t++)
#pragma unroll
        for (int j = 0; j < 4; j++) acc[t][j] = 0.f;

    for (int ch = 0; ch < NCH; ch++) {
        __syncthreads();
        // ---- stage A tile: 128 x 32 fp32 -> [xh|xl] ----
        for (int idx = tid; idx < 128 * (KC / 4); idx += 256) {
            int r = idx >> 3, c4 = idx & 7;
            int row = rowBase + r;
            float4 v = make_float4(0.f, 0.f, 0.f, 0.f);
            if (row < NN) v = *(const float4*)(X + (size_t)row * FIN + ch * KC + c4 * 4);
            float vv[4] = {v.x, v.y, v.z, v.w};
            unsigned short hs[4], ls[4];
#pragma unroll
            for (int j = 0; j < 4; j++) split2(vv[j], hs[j], ls[j]);
            *(uint2*)(As + r * PITCH + c4 * 4) = *(uint2*)hs;
            *(uint2*)(As + r * PITCH + 32 + c4 * 4) = *(uint2*)ls;
        }
        // ---- stage B tile: 32 x FOUT fp32 -> FOUT x [wh|wl] (transposed) ----
        for (int idx = tid; idx < KC * FOUT; idx += 256) {
            int k = idx / FOUT, n = idx % FOUT;
            unsigned short h, l;
            split2(__ldg(W + (size_t)(ch * KC + k) * FOUT + n), h, l);
            Bs[n * PITCH + k] = h;
            Bs[n * PITCH + 32 + k] = l;
        }
        __syncthreads();

        // ---- MMA: 2 k-steps of 16 per half ----
#pragma unroll
        for (int ks = 0; ks < 2; ks++) {
            int kb = ks * 16 + c2;
            uint32_t ah[4], al[4];
            ah[0] = *(const uint32_t*)(As + (wm + r4) * PITCH + kb);
            ah[1] = *(const uint32_t*)(As + (wm + r4 + 8) * PITCH + kb);
            ah[2] = *(const uint32_t*)(As + (wm + r4) * PITCH + kb + 8);
            ah[3] = *(const uint32_t*)(As + (wm + r4 + 8) * PITCH + kb + 8);
            al[0] = *(const uint32_t*)(As + (wm + r4) * PITCH + 32 + kb);
            al[1] = *(const uint32_t*)(As + (wm + r4 + 8) * PITCH + 32 + kb);
            al[2] = *(const uint32_t*)(As + (wm + r4) * PITCH + 32 + kb + 8);
            al[3] = *(const uint32_t*)(As + (wm + r4 + 8) * PITCH + 32 + kb + 8);
#pragma unroll
            for (int t = 0; t < NT; t++) {
                uint32_t bh[2], bl[2];
                bh[0] = *(const uint32_t*)(Bs + (t * 8 + r4) * PITCH + kb);
                bh[1] = *(const uint32_t*)(Bs + (t * 8 + r4) * PITCH + kb + 8);
                bl[0] = *(const uint32_t*)(Bs + (t * 8 + r4) * PITCH + 32 + kb);
                bl[1] = *(const uint32_t*)(Bs + (t * 8 + r4) * PITCH + 32 + kb + 8);
                mma16816(acc[t], ah, bh);
                mma16816(acc[t], al, bh);
                mma16816(acc[t], ah, bl);
            }
        }
    }

    // ---- epilogue: fp16 C stores + fused alpha logits ----
    int ra = rowBase + wm + r4;
    int rb = ra + 8;
#pragma unroll
    for (int t = 0; t < NT; t++) {
        int col = t * 8 + c2;
        if (ra < NN) {
            __half2 p = __floats2half2_rn(acc[t][0], acc[t][1]);
            *(__half2*)(C + (size_t)ra * FOUT + col) = p;
        }
        if (rb < NN) {
            __half2 p = __floats2half2_rn(acc[t][2], acc[t][3]);
            *(__half2*)(C + (size_t)rb * FOUT + col) = p;
        }
    }
    if (ALPHA) {
#pragma unroll
        for (int h = 0; h < 4; h++) {
            float pa_s = 0.f, pa_d = 0.f, pb_s = 0.f, pb_d = 0.f;
#pragma unroll
            for (int tt = 0; tt < 2; tt++) {
                int t = 2 * h + tt;
#pragma unroll
                for (int j = 0; j < 2; j++) {
                    int col = t * 8 + c2 + j;
                    float as_v = __ldg(asrc + col);
                    float ad_v = __ldg(adst + col);
                    pa_s += acc[t][j] * as_v;     pa_d += acc[t][j] * ad_v;
                    pb_s += acc[t][2 + j] * as_v; pb_d += acc[t][2 + j] * ad_v;
                }
            }
            pa_s += __shfl_xor_sync(0xffffffffu, pa_s, 1);
            pa_s += __shfl_xor_sync(0xffffffffu, pa_s, 2);
            pa_d += __shfl_xor_sync(0xffffffffu, pa_d, 1);
            pa_d += __shfl_xor_sync(0xffffffffu, pa_d, 2);
            pb_s += __shfl_xor_sync(0xffffffffu, pb_s, 1);
            pb_s += __shfl_xor_sync(0xffffffffu, pb_s, 2);
            pb_d += __shfl_xor_sync(0xffffffffu, pb_d, 1);
            pb_d += __shfl_xor_sync(0xffffffffu, pb_d, 2);
            if ((lane & 3) == 0) {
                if (ra < NN) { g_as[ra * 4 + h] = pa_s; g_ad[ra * 4 + h] = pa_d; }
                if (rb < NN) { g_as[rb * 4 + h] = pb_s; g_ad[rb * 4 + h] = pb_d; }
            }
        }
    }
}

// ---------------- CSR construction ----------------
__global__ void hist_kernel(const int* __restrict__ dsts) {
    int e = blockIdx.x * blockDim.x + threadIdx.x;
    if (e >= ETOT) return;
    int d = (e < EE) ? __ldg(dsts + e) : (e - EE);
    atomicAdd(&g_deg[d], 1);
}

__global__ void scan_kernel() {
    __shared__ int sums[1024];
    const int t = threadIdx.x;
    constexpr int CH = (NN + 1 + 1023) / 1024;
    const int base = t * CH;
    int s = 0;
    for (int j = 0; j < CH; j++) {
        int idx = base + j;
        if (idx < NN) s += g_deg[idx];
    }
    sums[t] = s;
    __syncthreads();
    for (int off = 1; off < 1024; off <<= 1) {
        int v = (t >= off) ? sums[t - off] : 0;
        __syncthreads();
        sums[t] += v;
        __syncthreads();
    }
    int run = (t == 0) ? 0 : sums[t - 1];
    for (int j = 0; j < CH; j++) {
        int idx = base + j;
        if (idx <= NN) {
            g_rowptr[idx] = run;
            if (idx < NN) {
                g_cursor[idx] = run;
                run += g_deg[idx];
            }
        }
    }
}

__global__ void fill_kernel(const int* __restrict__ srcs, const int* __restrict__ dsts) {
    int e = blockIdx.x * blockDim.x + threadIdx.x;
    if (e >= ETOT) return;
    int s, d;
    if (e < EE) { s = __ldg(srcs + e); d = __ldg(dsts + e); }
    else        { s = d = e - EE; }
    int pos = atomicAdd(&g_cursor[d], 1);
    g_csr[pos] = s;
}

// ---------------- prep (layer 3): attention logits from fp16 h ----------------
__global__ void prep40_kernel(const __half* __restrict__ h,
                              const float* __restrict__ a_src,
                              const float* __restrict__ a_dst) {
    int n = blockIdx.x * blockDim.x + threadIdx.x;
    if (n >= NN) return;
    const __half* hp = h + (size_t)n * 40;
    float s1 = 0.f, s2 = 0.f;
#pragma unroll
    for (int c = 0; c < 40; c++) {
        float v = __half2float(hp[c]);
        s1 += v * __ldg(a_src + c);
        s2 += v * __ldg(a_dst + c);
    }
    g_as[n] = s1;
    g_ad[n] = s2;
}

// ---------------- aggregate (layers 1-2): fp16 gather, fp32 out + relu ----------------
__global__ void agg_mid_kernel(const __half* __restrict__ h, const float* __restrict__ bias,
                               float* __restrict__ dest) {
    int gt = blockIdx.x * blockDim.x + threadIdx.x;
    int n = gt >> 4;
    int q = gt & 15;
    if (n >= NN) return;
    int hh = q >> 2;

    const float ad = g_ad[n * 4 + hh];
    const int beg = __ldg(g_rowptr + n);
    const int end = __ldg(g_rowptr + n + 1);

    float4 acc = make_float4(0.f, 0.f, 0.f, 0.f);
    float den = 0.f;
    for (int i = beg; i < end; i++) {
        int s = __ldg(g_csr + i);
        float v = __ldg(g_as + s * 4 + hh) + ad;
        v = v > 0.f ? v : 0.2f * v;
        float w = __expf(v);
        den += w;
        uint2 u = __ldg((const uint2*)(h + (size_t)s * 64) + q);
        float2 f01 = __half22float2(*(__half2*)&u.x);
        float2 f23 = __half22float2(*(__half2*)&u.y);
        acc.x += w * f01.x; acc.y += w * f01.y;
        acc.z += w * f23.x; acc.w += w * f23.y;
    }
    float inv = 1.f / (den + 1e-16f);
    float4 b = __ldg((const float4*)bias + q);
    float4 o;
    o.x = acc.x * inv + b.x; o.y = acc.y * inv + b.y;
    o.z = acc.z * inv + b.z; o.w = acc.w * inv + b.w;
    o.x = o.x > 0.f ? o.x : 0.f;
    o.y = o.y > 0.f ? o.y : 0.f;
    o.z = o.z > 0.f ? o.z : 0.f;
    o.w = o.w > 0.f ? o.w : 0.f;
    *(float4*)(dest + (size_t)n * 64 + q * 4) = o;
}

// ---------------- aggregate (layer 3): fp16 gather, fp32 out ----------------
__global__ void agg_out_kernel(const __half* __restrict__ h, const float* __restrict__ bias,
                               float* __restrict__ dest) {
    int gt = blockIdx.x * blockDim.x + threadIdx.x;
    int n = gt >> 4;
    int q = gt & 15;
    if (n >= NN) return;

    const float ad = g_ad[n];
    const int beg = __ldg(g_rowptr + n);
    const int end = __ldg(g_rowptr + n + 1);

    float4 acc = make_float4(0.f, 0.f, 0.f, 0.f);
    float den = 0.f;
    for (int i = beg; i < end; i++) {
        int s = __ldg(g_csr + i);
        float v = __ldg(g_as + s) + ad;
        v = v > 0.f ? v : 0.2f * v;
        float w = __expf(v);
        den += w;
        if (q < 10) {
            uint2 u = __ldg((const uint2*)(h + (size_t)s * 40) + q);
            float2 f01 = __half22float2(*(__half2*)&u.x);
            float2 f23 = __half22float2(*(__half2*)&u.y);
            acc.x += w * f01.x; acc.y += w * f01.y;
            acc.z += w * f23.x; acc.w += w * f23.y;
        }
    }
    if (q < 10) {
        float inv = 1.f / (den + 1e-16f);
        float4 b = __ldg((const float4*)bias + q);
        float4 o;
        o.x = acc.x * inv + b.x; o.y = acc.y * inv + b.y;
        o.z = acc.z * inv + b.z; o.w = acc.w * inv + b.w;
        *(float4*)(dest + (size_t)n * 40 + q * 4) = o;
    }
}

// ---------------- launch ----------------
extern "C" void kernel_launch(void* const* d_in, const int* in_sizes, int n_in,
                              void* d_out, int out_size) {
    const float* x = (const float*)d_in[0];
    const int* ei = (const int*)d_in[1];    // int32 (JAX x64 disabled)
    const float* W1 = (const float*)d_in[2];
    const float* asr1 = (const float*)d_in[3];
    const float* adr1 = (const float*)d_in[4];
    const float* b1 = (const float*)d_in[5];
    const float* W2 = (const float*)d_in[6];
    const float* asr2 = (const float*)d_in[7];
    const float* adr2 = (const float*)d_in[8];
    const float* b2 = (const float*)d_in[9];
    const float* W3 = (const float*)d_in[10];
    const float* asr3 = (const float*)d_in[11];
    const float* adr3 = (const float*)d_in[12];
    const float* b3 = (const float*)d_in[13];
    float* out = (float*)d_out;

    const int* esrc = ei;
    const int* edst = ei + EE;

    __half* p_h;
    float* p_feat;
    void* p_deg;
    cudaGetSymbolAddress((void**)&p_h, g_h);
    cudaGetSymbolAddress((void**)&p_feat, g_feat);
    cudaGetSymbolAddress(&p_deg, g_deg);

    const int mmaGrid = (NN + 127) / 128;  // 391
    const int edgeGrid = (ETOT + 255) / 256;
    const int aggGrid = (NN * 16 + 255) / 256;

    // Fork: CSR build on a side stream, overlapped with layer-1 GEMM.
    cudaStream_t s2;
    cudaStreamCreateWithFlags(&s2, cudaStreamNonBlocking);
    cudaEvent_t evFork, evJoin;
    cudaEventCreateWithFlags(&evFork, cudaEventDisableTiming);
    cudaEventCreateWithFlags(&evJoin, cudaEventDisableTiming);

    cudaEventRecord(evFork, 0);
    cudaStreamWaitEvent(s2, evFork, 0);
    cudaMemsetAsync(p_deg, 0, NN * sizeof(int), s2);
    hist_kernel<<<edgeGrid, 256, 0, s2>>>(edst);
    scan_kernel<<<1, 1024, 0, s2>>>();
    fill_kernel<<<edgeGrid, 256, 0, s2>>>(esrc, edst);
    cudaEventRecord(evJoin, s2);

    // ---------------- layer 1: 256 -> 4x16 ----------------
    mma_gemm<256, 64, true><<<mmaGrid, 256>>>(x, W1, p_h, asr1, adr1);
    cudaStreamWaitEvent(0, evJoin, 0);
    agg_mid_kernel<<<aggGrid, 256>>>(p_h, b1, p_feat);

    // ---------------- layer 2: 64 -> 4x16 ----------------
    mma_gemm<64, 64, true><<<mmaGrid, 256>>>(p_feat, W2, p_h, asr2, adr2);
    agg_mid_kernel<<<aggGrid, 256>>>(p_h, b2, p_feat);

    // ---------------- layer 3: 64 -> 1x40 ----------------
    mma_gemm<64, 40, false><<<mmaGrid, 256>>>(p_feat, W3, p_h, nullptr, nullptr);
    prep40_kernel<<<(NN + 255) / 256, 256>>>(p_h, asr3, adr3);
    agg_out_kernel<<<aggGrid, 256>>>(p_h, b3, out);
}